// round 12
// baseline (speedup 1.0000x reference)
#include <cuda_runtime.h>

// LIF scan: u = 0.5*u + x_t; o_t = (u >= 1); u -= o_t.
// Layout [B=32, T=16, C=128, H=32, W=32] fp32, contiguous.
// Inner slice per (b,t) = C*H*W = 131072 floats = 32768 float4.
// One thread per float4 site, sequential loop over T (stride 32768 float4).

#define INNER4 32768        // C*H*W / 4
#define TSTEPS 16

__global__ __launch_bounds__(256)
void lif_kernel(const float4* __restrict__ x, float4* __restrict__ o)
{
    const int i = blockIdx.x * blockDim.x + threadIdx.x;   // 0 .. 32*32768-1
    const int b     = i >> 15;
    const int inner = i & (INNER4 - 1);
    int idx = b * (TSTEPS * INNER4) + inner;               // max 16,777,215 < 2^31

    float ux = 0.f, uy = 0.f, uz = 0.f, uw = 0.f;

#pragma unroll
    for (int t = 0; t < TSTEPS; ++t) {
        const float4 xt = x[idx];

        ux = fmaf(0.5f, ux, xt.x);
        uy = fmaf(0.5f, uy, xt.y);
        uz = fmaf(0.5f, uz, xt.z);
        uw = fmaf(0.5f, uw, xt.w);

        float4 ot;
        ot.x = (ux >= 1.0f) ? 1.0f : 0.0f;
        ot.y = (uy >= 1.0f) ? 1.0f : 0.0f;
        ot.z = (uz >= 1.0f) ? 1.0f : 0.0f;
        ot.w = (uw >= 1.0f) ? 1.0f : 0.0f;

        ux -= ot.x;
        uy -= ot.y;
        uz -= ot.z;
        uw -= ot.w;

        o[idx] = ot;
        idx += INNER4;
    }
}

extern "C" void kernel_launch(void* const* d_in, const int* in_sizes, int n_in,
                              void* d_out, int out_size)
{
    const float4* x = (const float4*)d_in[0];
    float4* o = (float4*)d_out;

    // total sites = B * C*H*W / 4 = 32 * 32768 = 1,048,576 threads
    const int threads = 256;
    const int blocks = (32 * INNER4) / threads;            // 4096
    lif_kernel<<<blocks, threads>>>(x, o);
}

// round 13
// speedup vs baseline: 1.0144x; 1.0144x over previous
#include <cuda_runtime.h>

// LIF scan: u = 0.5*u + x_t; o_t = (u >= 1); u -= o_t.
// Layout [B=32, T=16, C=128, H=32, W=32] fp32, contiguous.
// Inner slice per (b,t) = C*H*W = 131072 floats = 32768 float4.
// One thread per float4 site, sequential loop over T (stride 32768 float4).

#define INNER4 32768        // C*H*W / 4
#define TSTEPS 16

__global__ __launch_bounds__(256)
void lif_kernel(const float4* __restrict__ x, float4* __restrict__ o)
{
    const int i = blockIdx.x * blockDim.x + threadIdx.x;   // 0 .. 32*32768-1
    const int b     = i >> 15;
    const int inner = i & (INNER4 - 1);
    int idx = b * (TSTEPS * INNER4) + inner;               // max 16,777,215 < 2^31

    float ux = 0.f, uy = 0.f, uz = 0.f, uw = 0.f;

#pragma unroll
    for (int t = 0; t < TSTEPS; ++t) {
        const float4 xt = x[idx];

        ux = fmaf(0.5f, ux, xt.x);
        uy = fmaf(0.5f, uy, xt.y);
        uz = fmaf(0.5f, uz, xt.z);
        uw = fmaf(0.5f, uw, xt.w);

        float4 ot;
        ot.x = (ux >= 1.0f) ? 1.0f : 0.0f;
        ot.y = (uy >= 1.0f) ? 1.0f : 0.0f;
        ot.z = (uz >= 1.0f) ? 1.0f : 0.0f;
        ot.w = (uw >= 1.0f) ? 1.0f : 0.0f;

        ux -= ot.x;
        uy -= ot.y;
        uz -= ot.z;
        uw -= ot.w;

        o[idx] = ot;
        idx += INNER4;
    }
}

extern "C" void kernel_launch(void* const* d_in, const int* in_sizes, int n_in,
                              void* d_out, int out_size)
{
    const float4* x = (const float4*)d_in[0];
    float4* o = (float4*)d_out;

    // total sites = B * C*H*W / 4 = 32 * 32768 = 1,048,576 threads
    const int threads = 256;
    const int blocks = (32 * INNER4) / threads;            // 4096
    lif_kernel<<<blocks, threads>>>(x, o);
}